// round 16
// baseline (speedup 1.0000x reference)
#include <cuda_runtime.h>
#include <cuda_fp16.h>
#include <cstdint>

#define SEQ   2048
#define BATCH 2
#define NH    16
#define HD    64
#define DM    1024
#define WIN   256
#define MROWS (BATCH * SEQ)          // 4096

// ---------------------------------------------------------------------------
// Device scratch. Plain fp16 activations/weights (fp32 accumulate in MMA).
// ---------------------------------------------------------------------------
__device__ __half g_xh[(size_t)MROWS * DM];
__device__ __half g_Ch[(size_t)MROWS * DM];
__device__ __half g_Qh[(size_t)MROWS * DM];
__device__ __half g_Kh[(size_t)MROWS * DM];
__device__ __half g_Vh[(size_t)MROWS * DM];
__device__ __half g_Bh[(size_t)4 * DM * DM];   // W^T as [n][k]; q,k,v,o

// ---------------------------------------------------------------------------
// PTX helpers
// ---------------------------------------------------------------------------
__device__ __forceinline__ uint32_t smem_u32(const void* p) {
    uint32_t a;
    asm("{ .reg .u64 t; cvta.to.shared.u64 t, %1; cvt.u32.u64 %0, t; }"
        : "=r"(a) : "l"(p));
    return a;
}

__device__ __forceinline__ void cpasync16(uint32_t dst, const void* src) {
    asm volatile("cp.async.cg.shared.global [%0], [%1], 16;"
                 :: "r"(dst), "l"(src));
}
#define CP_COMMIT() asm volatile("cp.async.commit_group;" ::: "memory")
#define CP_WAIT(n)  asm volatile("cp.async.wait_group %0;" :: "n"(n) : "memory")

__device__ __forceinline__ void ldsm4(uint32_t* r, uint32_t addr) {
    asm volatile("ldmatrix.sync.aligned.m8n8.x4.shared.b16 {%0,%1,%2,%3}, [%4];"
                 : "=r"(r[0]), "=r"(r[1]), "=r"(r[2]), "=r"(r[3]) : "r"(addr));
}
__device__ __forceinline__ void ldsm4t(uint32_t* r, uint32_t addr) {
    asm volatile("ldmatrix.sync.aligned.m8n8.x4.trans.shared.b16 {%0,%1,%2,%3}, [%4];"
                 : "=r"(r[0]), "=r"(r[1]), "=r"(r[2]), "=r"(r[3]) : "r"(addr));
}

__device__ __forceinline__ void mma16816(float* c, const uint32_t* a, const uint32_t* b) {
    asm volatile(
        "mma.sync.aligned.m16n8k16.row.col.f32.f16.f16.f32 "
        "{%0,%1,%2,%3}, {%4,%5,%6,%7}, {%8,%9}, {%0,%1,%2,%3};"
        : "+f"(c[0]), "+f"(c[1]), "+f"(c[2]), "+f"(c[3])
        : "r"(a[0]), "r"(a[1]), "r"(a[2]), "r"(a[3]), "r"(b[0]), "r"(b[1]));
}

__device__ __forceinline__ uint32_t pkh(float a, float b) {
    __half2 t = __floats2half2_rn(a, b);
    return *reinterpret_cast<uint32_t*>(&t);
}

// ---------------------------------------------------------------------------
// Convert fp32 x -> fp16
// ---------------------------------------------------------------------------
__global__ __launch_bounds__(256) void split_kernel(const float* __restrict__ src)
{
    int i = blockIdx.x * 256 + threadIdx.x;
    float4 v = ((const float4*)src)[i];
    ((uint32_t*)g_xh)[2 * i]     = pkh(v.x, v.y);
    ((uint32_t*)g_xh)[2 * i + 1] = pkh(v.z, v.w);
}

// Transpose + convert weights: g_Bh[z][n][k] = fp16(W_z[k][n])
__global__ __launch_bounds__(256) void splitT_kernel(
    const float* __restrict__ w0, const float* __restrict__ w1,
    const float* __restrict__ w2, const float* __restrict__ w3)
{
    __shared__ float t[32][33];
    const int z = blockIdx.z;
    const float* __restrict__ W = (z == 0) ? w0 : (z == 1) ? w1 : (z == 2) ? w2 : w3;
    const int tx = threadIdx.x, ty = threadIdx.y;
    const int bx = blockIdx.x, by = blockIdx.y;
#pragma unroll
    for (int i = 0; i < 4; i++) {
        int k = by * 32 + ty + i * 8;
        int n = bx * 32 + tx;
        t[ty + i * 8][tx] = W[(size_t)k * DM + n];
    }
    __syncthreads();
    size_t base = (size_t)z * DM * DM;
#pragma unroll
    for (int i = 0; i < 4; i++) {
        int n = bx * 32 + ty + i * 8;
        int k = by * 32 + tx;
        g_Bh[base + (size_t)n * DM + k] = __float2half_rn(t[tx][ty + i * 8]);
    }
}

// ---------------------------------------------------------------------------
// fp16 HMMA GEMM, PERSISTENT (simple per-tile pipeline restart; tile address
// math stays OUTSIDE the k-loop). CTA tile 256x128, 512 threads (1 CTA/SM),
// kTile 64, 2-stage cp.async, single barrier per iteration.
// mode 0: 384 tiles over 148 CTAs (no wave tail); x -> Q(/8), K, V.
// mode 1: 128 tiles over 128 CTAs (single wave); C -> out fp32 (+bias).
// ---------------------------------------------------------------------------
#define MMBUF_A 36864                      // 256 rows * 144 B
#define MMBUF_B 18432                      // 128 rows * 144 B
#define MMSTAGE (MMBUF_A + MMBUF_B)        // 55296
#define MM_SMEM (2 * MMSTAGE)              // 110592
#define NKIT    16                         // 1024 / 64

__global__ __launch_bounds__(512, 1) void mm_kernel(
    const float* __restrict__ bias, float* __restrict__ outp, int mode, int ntiles)
{
    extern __shared__ char smc[];
    const uint32_t sm0 = smem_u32(smc);
    const int tid  = threadIdx.x;
    const int lane = tid & 31;
    const int wid  = tid >> 5;
    const int warpM = wid & 3;             // 4 x 64 rows
    const int warpN = wid >> 2;            // 4 x 32 cols
    const int NC   = gridDim.x;

    const __half* __restrict__ Ah = (mode == 0) ? g_xh : g_Ch;

    const int a_r  = (lane & 7) + ((lane >> 3) & 1) * 8;
    const int a_kc = (lane >> 4) * 8;
    const int b_n  = (lane & 7) + (lane >> 4) * 8;
    const int b_kc = ((lane >> 3) & 1) * 8;

// A: 256 rows * 8 chunks = 2048; B: 128 rows * 8 chunks = 1024; total 3072 = 6*512
#define LOAD_STAGE(it_)                                                          \
    do {                                                                         \
        int k0_ = (it_) * 64;                                                    \
        uint32_t sb_ = sm0 + ((it_) & 1) * MMSTAGE;                              \
        _Pragma("unroll")                                                        \
        for (int i_ = 0; i_ < 6; i_++) {                                         \
            int idx_ = tid + i_ * 512;                                           \
            if (idx_ < 2048) {                                                   \
                int r_ = idx_ >> 3, sg_ = idx_ & 7;                              \
                cpasync16(sb_ + r_ * 144 + sg_ * 16,                             \
                          Ah + (size_t)(row0 + r_) * DM + k0_ + sg_ * 8);        \
            } else {                                                             \
                int j_ = idx_ - 2048;                                            \
                int r_ = j_ >> 3, sg_ = j_ & 7;                                  \
                cpasync16(sb_ + MMBUF_A + r_ * 144 + sg_ * 16,                   \
                          Bh + (size_t)(col0 + r_) * DM + k0_ + sg_ * 8);        \
            }                                                                    \
        }                                                                        \
    } while (0)

    for (int t = blockIdx.x; t < ntiles; t += NC) {
        const int zz   = (mode == 0) ? (t >> 7) : 3;
        const int rem  = t & 127;
        const int row0 = (rem >> 3) * 256;
        const int col0 = (rem & 7) * 128;
        const __half* __restrict__ Bh = g_Bh + (size_t)zz * DM * DM;

        float acc[4][4][4];
#pragma unroll
        for (int a = 0; a < 4; a++)
#pragma unroll
            for (int b = 0; b < 4; b++)
#pragma unroll
                for (int c = 0; c < 4; c++) acc[a][b][c] = 0.f;

        LOAD_STAGE(0);
        CP_COMMIT();

        for (int it = 0; it < NKIT; it++) {
            CP_WAIT(0);
            __syncthreads();
            if (it + 1 < NKIT) {
                LOAD_STAGE(it + 1);
                CP_COMMIT();
            }

            uint32_t sb = sm0 + (it & 1) * MMSTAGE;
#pragma unroll
            for (int kk = 0; kk < 4; kk++) {
                uint32_t bh[2][4];
#pragma unroll
                for (int np = 0; np < 2; np++) {
                    int n = warpN * 32 + np * 16 + b_n;
                    uint32_t off = (uint32_t)(n * 144 + (kk * 16 + b_kc) * 2);
                    ldsm4(bh[np], sb + MMBUF_A + off);
                }
#pragma unroll
                for (int mp = 0; mp < 2; mp++) {
                    uint32_t ah[2][4];
#pragma unroll
                    for (int mi = 0; mi < 2; mi++) {
                        int r = warpM * 64 + (mp * 2 + mi) * 16 + a_r;
                        uint32_t off = (uint32_t)(r * 144 + (kk * 16 + a_kc) * 2);
                        ldsm4(ah[mi], sb + off);
                    }
#pragma unroll
                    for (int mi = 0; mi < 2; mi++)
#pragma unroll
                        for (int nb = 0; nb < 4; nb++)
                            mma16816(acc[mp * 2 + mi][nb], ah[mi],
                                     &bh[nb >> 1][(nb & 1) * 2]);
                }
            }
        }

        if (mode == 0) {
            __half* __restrict__ Oh = (zz == 0) ? g_Qh : (zz == 1) ? g_Kh : g_Vh;
            const float sc = (zz == 0) ? 0.125f : 1.0f;
#pragma unroll
            for (int mb = 0; mb < 4; mb++) {
                int r = row0 + warpM * 64 + mb * 16 + (lane >> 2);
#pragma unroll
                for (int nb = 0; nb < 4; nb++) {
                    int c = col0 + warpN * 32 + nb * 8 + (lane & 3) * 2;
                    *(uint32_t*)&Oh[(size_t)r * DM + c] =
                        pkh(acc[mb][nb][0] * sc, acc[mb][nb][1] * sc);
                    *(uint32_t*)&Oh[(size_t)(r + 8) * DM + c] =
                        pkh(acc[mb][nb][2] * sc, acc[mb][nb][3] * sc);
                }
            }
        } else {
#pragma unroll
            for (int mb = 0; mb < 4; mb++) {
                int r = row0 + warpM * 64 + mb * 16 + (lane >> 2);
#pragma unroll
                for (int nb = 0; nb < 4; nb++) {
                    int c = col0 + warpN * 32 + nb * 8 + (lane & 3) * 2;
                    float2 v0 = make_float2(acc[mb][nb][0] + bias[c], acc[mb][nb][1] + bias[c + 1]);
                    float2 v1 = make_float2(acc[mb][nb][2] + bias[c], acc[mb][nb][3] + bias[c + 1]);
                    *(float2*)&outp[(size_t)r * DM + c]       = v0;
                    *(float2*)&outp[(size_t)(r + 8) * DM + c] = v1;
                }
            }
        }
    }
#undef LOAD_STAGE
}

// ---------------------------------------------------------------------------
// fp16 HMMA flash attention, 64-key chunks, split-KEY warp specialization,
// fixed-max softmax (scores bounded; masked -> exp 0), plain-add merge.
// Smem: [Q][K0][K1][V0][V1] (5 x 64x72 fp16).
// ---------------------------------------------------------------------------
#define KST 72
#define ATILE (64 * KST)
#define ATB   (ATILE * 2)                        // 9216
#define ATTN_SMEM (5 * ATB)                      // 46080

__global__ __launch_bounds__(256, 2) void attn_kernel()
{
    extern __shared__ __half smb[];
    const uint32_t sm0 = smem_u32(smb);

    const int qt = blockIdx.x;
    const int bh = blockIdx.y;
    const int b  = bh >> 4;
    const int h  = bh & 15;
    const int tid  = threadIdx.x;
    const int w    = tid >> 5;
    const int wq   = w & 3;
    const int wk   = w >> 2;
    const int lane = tid & 31;
    const int qs = qt * 64;

    const size_t hoff = (size_t)b * SEQ * DM + h * HD;
    const __half* __restrict__ Qg = g_Qh + hoff;
    const __half* __restrict__ Kg = g_Kh + hoff;
    const __half* __restrict__ Vg = g_Vh + hoff;

    int ks0 = qs - WIN; if (ks0 < 0) ks0 = 0;
    int ke  = qs + 64 + WIN; if (ke > SEQ) ke = SEQ;
    const int nc = (ke - ks0) >> 6;

#define PREF(ci_)                                                                \
    do {                                                                         \
        int kb_ = ks0 + (ci_) * 64;                                              \
        uint32_t st_ = ((ci_) & 1) * ATB;                                        \
        _Pragma("unroll")                                                        \
        for (int i_ = 0; i_ < 2; i_++) {                                         \
            int idx_ = tid + i_ * 256;                                           \
            int r_ = idx_ >> 3, c_ = idx_ & 7;                                   \
            uint32_t doff_ = (uint32_t)(r_ * KST + c_ * 8) * 2;                  \
            size_t g_ = (size_t)(kb_ + r_) * DM + c_ * 8;                        \
            cpasync16(sm0 + 1 * ATB + st_ + doff_, Kg + g_);                     \
            cpasync16(sm0 + 3 * ATB + st_ + doff_, Vg + g_);                     \
        }                                                                        \
    } while (0)

    PREF(0);
    CP_COMMIT();

    for (int i = tid; i < 64 * 8; i += 256) {
        int r = i >> 3, c = i & 7;
        *(uint4*)&smb[r * KST + c * 8] = *(const uint4*)(Qg + (size_t)(qs + r) * DM + c * 8);
    }
    __syncthreads();

    const int a_r  = (lane & 7) + ((lane >> 3) & 1) * 8;
    const int a_kc = (lane >> 4) * 8;
    uint32_t qa[4][4];
#pragma unroll
    for (int kk = 0; kk < 4; kk++) {
        uint32_t off = (uint32_t)((wq * 16 + a_r) * KST + kk * 16 + a_kc) * 2;
        ldsm4(qa[kk], sm0 + off);
    }

    float O[8][4];
#pragma unroll
    for (int t = 0; t < 8; t++)
#pragma unroll
        for (int e = 0; e < 4; e++) O[t][e] = 0.f;
    float l0 = 0.f, l1 = 0.f;

    const int b_n  = (lane & 7) + (lane >> 4) * 8;
    const int b_kc = ((lane >> 3) & 1) * 8;
    const int v_r  = lane & 15;
    const int v_c  = (lane >> 4) * 8;
    const int q0 = qs + wq * 16 + (lane >> 2);
    const int q1 = q0 + 8;

    for (int ci = 0; ci < nc; ci++) {
        const int kb = ks0 + ci * 64;
        CP_WAIT(0);
        __syncthreads();
        if (ci + 1 < nc) {
            PREF(ci + 1);
            CP_COMMIT();
        }

        const uint32_t Khb = sm0 + 1 * ATB + (ci & 1) * ATB;
        const uint32_t Vhb = sm0 + 3 * ATB + (ci & 1) * ATB;

        float S[4][4];
#pragma unroll
        for (int t = 0; t < 4; t++)
#pragma unroll
            for (int e = 0; e < 4; e++) S[t][e] = 0.f;

#pragma unroll
        for (int kk = 0; kk < 4; kk++) {
#pragma unroll
            for (int nt = 0; nt < 2; nt++) {
                uint32_t kh[4];
                uint32_t off = (uint32_t)((wk * 32 + nt * 16 + b_n) * KST + kk * 16 + b_kc) * 2;
                ldsm4(kh, Khb + off);
                mma16816(S[nt * 2 + 0], qa[kk], &kh[0]);
                mma16816(S[nt * 2 + 1], qa[kk], &kh[2]);
            }
        }

        const int kc = kb + wk * 32 + 2 * (lane & 3);
#pragma unroll
        for (int j = 0; j < 4; j++) {
            int d0 = kc + j * 8 - q0 + WIN;
            S[j][0] = ((unsigned)d0 <= 2u * WIN)       ? S[j][0] : -1e30f;
            S[j][1] = ((unsigned)(d0 + 1) <= 2u * WIN) ? S[j][1] : -1e30f;
            S[j][2] = ((unsigned)(d0 - 8) <= 2u * WIN) ? S[j][2] : -1e30f;
            S[j][3] = ((unsigned)(d0 - 7) <= 2u * WIN) ? S[j][3] : -1e30f;
        }
#pragma unroll
        for (int j = 0; j < 4; j++) {
            S[j][0] = __expf(S[j][0]);
            S[j][1] = __expf(S[j][1]);
            S[j][2] = __expf(S[j][2]);
            S[j][3] = __expf(S[j][3]);
            l0 += S[j][0] + S[j][1];
            l1 += S[j][2] + S[j][3];
        }

#pragma unroll
        for (int kk = 0; kk < 2; kk++) {
            uint32_t pa[4];
            const float* sj0 = S[2 * kk];
            const float* sj1 = S[2 * kk + 1];
            pa[0] = pkh(sj0[0], sj0[1]);
            pa[1] = pkh(sj0[2], sj0[3]);
            pa[2] = pkh(sj1[0], sj1[1]);
            pa[3] = pkh(sj1[2], sj1[3]);
#pragma unroll
            for (int nt = 0; nt < 4; nt++) {
                uint32_t vh[4];
                uint32_t off = (uint32_t)((wk * 32 + kk * 16 + v_r) * KST + nt * 16 + v_c) * 2;
                ldsm4t(vh, Vhb + off);
                mma16816(O[nt * 2 + 0], pa, &vh[0]);
                mma16816(O[nt * 2 + 1], pa, &vh[2]);
            }
        }
    }

    l0 += __shfl_xor_sync(0xffffffffu, l0, 1);
    l0 += __shfl_xor_sync(0xffffffffu, l0, 2);
    l1 += __shfl_xor_sync(0xffffffffu, l1, 1);
    l1 += __shfl_xor_sync(0xffffffffu, l1, 2);

    __syncthreads();
    float* mrg = (float*)smb;
    const int slot = (wq * 32 + lane) * 35;
    if (wk == 1) {
        mrg[slot + 0] = l0; mrg[slot + 1] = l1;
#pragma unroll
        for (int t = 0; t < 8; t++)
#pragma unroll
            for (int e = 0; e < 4; e++) mrg[slot + 2 + t * 4 + e] = O[t][e];
    }
    __syncthreads();
    if (wk == 0) {
        float L0 = l0 + mrg[slot + 0];
        float L1 = l1 + mrg[slot + 1];
        float inv0 = 1.f / L0, inv1 = 1.f / L1;
#pragma unroll
        for (int t = 0; t < 8; t++) {
            float v0 = (O[t][0] + mrg[slot + 2 + t * 4 + 0]) * inv0;
            float v1 = (O[t][1] + mrg[slot + 2 + t * 4 + 1]) * inv0;
            float v2 = (O[t][2] + mrg[slot + 2 + t * 4 + 2]) * inv1;
            float v3 = (O[t][3] + mrg[slot + 2 + t * 4 + 3]) * inv1;
            int c = h * HD + t * 8 + 2 * (lane & 3);
            *(uint32_t*)&g_Ch[((size_t)b * SEQ + q0) * DM + c] = pkh(v0, v1);
            *(uint32_t*)&g_Ch[((size_t)b * SEQ + q1) * DM + c] = pkh(v2, v3);
        }
    }
#undef PREF
}

// ---------------------------------------------------------------------------
extern "C" void kernel_launch(void* const* d_in, const int* in_sizes, int n_in,
                              void* d_out, int out_size)
{
    const float* x  = (const float*)d_in[0];
    const float* Wq = (const float*)d_in[1];
    const float* Wk = (const float*)d_in[2];
    const float* Wv = (const float*)d_in[3];
    const float* Wo = (const float*)d_in[4];
    const float* bo = (const float*)d_in[5];
    float* out = (float*)d_out;

    cudaFuncSetAttribute(mm_kernel, cudaFuncAttributeMaxDynamicSharedMemorySize, MM_SMEM);
    cudaFuncSetAttribute(attn_kernel, cudaFuncAttributeMaxDynamicSharedMemorySize, ATTN_SMEM);

    split_kernel<<<(MROWS * DM) / (4 * 256), 256>>>(x);
    splitT_kernel<<<dim3(DM / 32, DM / 32, 4), dim3(32, 8)>>>(Wq, Wk, Wv, Wo);

    // QKV: 384 tiles over 148 persistent CTAs (no wave tail)
    mm_kernel<<<148, 512, MM_SMEM>>>(nullptr, nullptr, 0, 384);

    attn_kernel<<<dim3(SEQ / 64, BATCH * NH), 256, ATTN_SMEM>>>();

    // Output projection: 128 tiles, one per CTA (single wave)
    mm_kernel<<<128, 512, MM_SMEM>>>(bo, out, 1, 128);
}

// round 17
// speedup vs baseline: 1.0066x; 1.0066x over previous
#include <cuda_runtime.h>
#include <cuda_fp16.h>
#include <cstdint>

#define SEQ   2048
#define BATCH 2
#define NH    16
#define HD    64
#define DM    1024
#define WIN   256
#define MROWS (BATCH * SEQ)          // 4096

// ---------------------------------------------------------------------------
// Device scratch. Plain fp16 activations/weights (fp32 accumulate in MMA).
// ---------------------------------------------------------------------------
__device__ __half g_xh[(size_t)MROWS * DM];
__device__ __half g_Ch[(size_t)MROWS * DM];
__device__ __half g_Qh[(size_t)MROWS * DM];
__device__ __half g_Kh[(size_t)MROWS * DM];
__device__ __half g_Vh[(size_t)MROWS * DM];
__device__ __half g_Bh[(size_t)4 * DM * DM];   // W^T as [n][k]; q,k,v,o

// ---------------------------------------------------------------------------
// PTX helpers
// ---------------------------------------------------------------------------
__device__ __forceinline__ uint32_t smem_u32(const void* p) {
    uint32_t a;
    asm("{ .reg .u64 t; cvta.to.shared.u64 t, %1; cvt.u32.u64 %0, t; }"
        : "=r"(a) : "l"(p));
    return a;
}

__device__ __forceinline__ void cpasync16(uint32_t dst, const void* src) {
    asm volatile("cp.async.cg.shared.global [%0], [%1], 16;"
                 :: "r"(dst), "l"(src));
}
#define CP_COMMIT() asm volatile("cp.async.commit_group;" ::: "memory")
#define CP_WAIT(n)  asm volatile("cp.async.wait_group %0;" :: "n"(n) : "memory")

__device__ __forceinline__ void ldsm4(uint32_t* r, uint32_t addr) {
    asm volatile("ldmatrix.sync.aligned.m8n8.x4.shared.b16 {%0,%1,%2,%3}, [%4];"
                 : "=r"(r[0]), "=r"(r[1]), "=r"(r[2]), "=r"(r[3]) : "r"(addr));
}
__device__ __forceinline__ void ldsm4t(uint32_t* r, uint32_t addr) {
    asm volatile("ldmatrix.sync.aligned.m8n8.x4.trans.shared.b16 {%0,%1,%2,%3}, [%4];"
                 : "=r"(r[0]), "=r"(r[1]), "=r"(r[2]), "=r"(r[3]) : "r"(addr));
}

__device__ __forceinline__ void mma16816(float* c, const uint32_t* a, const uint32_t* b) {
    asm volatile(
        "mma.sync.aligned.m16n8k16.row.col.f32.f16.f16.f32 "
        "{%0,%1,%2,%3}, {%4,%5,%6,%7}, {%8,%9}, {%0,%1,%2,%3};"
        : "+f"(c[0]), "+f"(c[1]), "+f"(c[2]), "+f"(c[3])
        : "r"(a[0]), "r"(a[1]), "r"(a[2]), "r"(a[3]), "r"(b[0]), "r"(b[1]));
}

__device__ __forceinline__ uint32_t pkh(float a, float b) {
    __half2 t = __floats2half2_rn(a, b);
    return *reinterpret_cast<uint32_t*>(&t);
}

// ---------------------------------------------------------------------------
// Convert fp32 x -> fp16
// ---------------------------------------------------------------------------
__global__ __launch_bounds__(256) void split_kernel(const float* __restrict__ src)
{
    int i = blockIdx.x * 256 + threadIdx.x;
    float4 v = ((const float4*)src)[i];
    ((uint32_t*)g_xh)[2 * i]     = pkh(v.x, v.y);
    ((uint32_t*)g_xh)[2 * i + 1] = pkh(v.z, v.w);
}

// Transpose + convert weights: g_Bh[z][n][k] = fp16(W_z[k][n])
__global__ __launch_bounds__(256) void splitT_kernel(
    const float* __restrict__ w0, const float* __restrict__ w1,
    const float* __restrict__ w2, const float* __restrict__ w3)
{
    __shared__ float t[32][33];
    const int z = blockIdx.z;
    const float* __restrict__ W = (z == 0) ? w0 : (z == 1) ? w1 : (z == 2) ? w2 : w3;
    const int tx = threadIdx.x, ty = threadIdx.y;
    const int bx = blockIdx.x, by = blockIdx.y;
#pragma unroll
    for (int i = 0; i < 4; i++) {
        int k = by * 32 + ty + i * 8;
        int n = bx * 32 + tx;
        t[ty + i * 8][tx] = W[(size_t)k * DM + n];
    }
    __syncthreads();
    size_t base = (size_t)z * DM * DM;
#pragma unroll
    for (int i = 0; i < 4; i++) {
        int n = bx * 32 + ty + i * 8;
        int k = by * 32 + tx;
        g_Bh[base + (size_t)n * DM + k] = __float2half_rn(t[tx][ty + i * 8]);
    }
}

// ---------------------------------------------------------------------------
// fp16 HMMA GEMM (round-15 config). CTA 256x128, 512 threads (1 CTA/SM),
// kTile 64, 2-stage cp.async, single barrier per iteration. Warp = 64x32.
// mode 0: x -> Q(/8), K, V. mode 1: C -> out fp32 (+bias).
// ---------------------------------------------------------------------------
#define MMBUF_A 36864                      // 256 rows * 144 B
#define MMBUF_B 18432                      // 128 rows * 144 B
#define MMSTAGE (MMBUF_A + MMBUF_B)        // 55296
#define MM_SMEM (2 * MMSTAGE)              // 110592
#define NKIT    16                         // 1024 / 64

__global__ __launch_bounds__(512, 1) void mm_kernel(
    const float* __restrict__ bias, float* __restrict__ outp, int mode)
{
    extern __shared__ char smc[];
    const uint32_t sm0 = smem_u32(smc);
    const int tid  = threadIdx.x;
    const int lane = tid & 31;
    const int wid  = tid >> 5;
    const int warpM = wid & 3;             // 4 x 64 rows
    const int warpN = wid >> 2;            // 4 x 32 cols
    const int row0 = blockIdx.y * 256;
    const int col0 = blockIdx.x * 128;
    const int z    = blockIdx.z;
    const int zz   = (mode == 0) ? z : 3;

    const __half* __restrict__ Ah = (mode == 0) ? g_xh : g_Ch;
    const __half* __restrict__ Bh = g_Bh + (size_t)zz * DM * DM;

    float acc[4][4][4];
#pragma unroll
    for (int a = 0; a < 4; a++)
#pragma unroll
        for (int b = 0; b < 4; b++)
#pragma unroll
            for (int c = 0; c < 4; c++) acc[a][b][c] = 0.f;

    const int a_r  = (lane & 7) + ((lane >> 3) & 1) * 8;
    const int a_kc = (lane >> 4) * 8;
    const int b_n  = (lane & 7) + (lane >> 4) * 8;
    const int b_kc = ((lane >> 3) & 1) * 8;

// A: 256 rows * 8 chunks = 2048; B: 128 rows * 8 chunks = 1024; total 3072 = 6*512
#define LOAD_STAGE(it_)                                                          \
    do {                                                                         \
        int k0_ = (it_) * 64;                                                    \
        uint32_t sb_ = sm0 + ((it_) & 1) * MMSTAGE;                              \
        _Pragma("unroll")                                                        \
        for (int i_ = 0; i_ < 6; i_++) {                                         \
            int idx_ = tid + i_ * 512;                                           \
            if (idx_ < 2048) {                                                   \
                int r_ = idx_ >> 3, sg_ = idx_ & 7;                              \
                cpasync16(sb_ + r_ * 144 + sg_ * 16,                             \
                          Ah + (size_t)(row0 + r_) * DM + k0_ + sg_ * 8);        \
            } else {                                                             \
                int j_ = idx_ - 2048;                                            \
                int r_ = j_ >> 3, sg_ = j_ & 7;                                  \
                cpasync16(sb_ + MMBUF_A + r_ * 144 + sg_ * 16,                   \
                          Bh + (size_t)(col0 + r_) * DM + k0_ + sg_ * 8);        \
            }                                                                    \
        }                                                                        \
    } while (0)

    LOAD_STAGE(0);
    CP_COMMIT();

    for (int it = 0; it < NKIT; it++) {
        CP_WAIT(0);
        __syncthreads();
        if (it + 1 < NKIT) {
            LOAD_STAGE(it + 1);
            CP_COMMIT();
        }

        uint32_t sb = sm0 + (it & 1) * MMSTAGE;
#pragma unroll
        for (int kk = 0; kk < 4; kk++) {
            uint32_t bh[2][4];
#pragma unroll
            for (int np = 0; np < 2; np++) {
                int n = warpN * 32 + np * 16 + b_n;
                uint32_t off = (uint32_t)(n * 144 + (kk * 16 + b_kc) * 2);
                ldsm4(bh[np], sb + MMBUF_A + off);
            }
#pragma unroll
            for (int mp = 0; mp < 2; mp++) {
                uint32_t ah[2][4];
#pragma unroll
                for (int mi = 0; mi < 2; mi++) {
                    int r = warpM * 64 + (mp * 2 + mi) * 16 + a_r;
                    uint32_t off = (uint32_t)(r * 144 + (kk * 16 + a_kc) * 2);
                    ldsm4(ah[mi], sb + off);
                }
#pragma unroll
                for (int mi = 0; mi < 2; mi++)
#pragma unroll
                    for (int nb = 0; nb < 4; nb++)
                        mma16816(acc[mp * 2 + mi][nb], ah[mi],
                                 &bh[nb >> 1][(nb & 1) * 2]);
            }
        }
    }

    if (mode == 0) {
        __half* __restrict__ Oh = (z == 0) ? g_Qh : (z == 1) ? g_Kh : g_Vh;
        const float sc = (z == 0) ? 0.125f : 1.0f;
#pragma unroll
        for (int mb = 0; mb < 4; mb++) {
            int r = row0 + warpM * 64 + mb * 16 + (lane >> 2);
#pragma unroll
            for (int nb = 0; nb < 4; nb++) {
                int c = col0 + warpN * 32 + nb * 8 + (lane & 3) * 2;
                *(uint32_t*)&Oh[(size_t)r * DM + c] =
                    pkh(acc[mb][nb][0] * sc, acc[mb][nb][1] * sc);
                *(uint32_t*)&Oh[(size_t)(r + 8) * DM + c] =
                    pkh(acc[mb][nb][2] * sc, acc[mb][nb][3] * sc);
            }
        }
    } else {
#pragma unroll
        for (int mb = 0; mb < 4; mb++) {
            int r = row0 + warpM * 64 + mb * 16 + (lane >> 2);
#pragma unroll
            for (int nb = 0; nb < 4; nb++) {
                int c = col0 + warpN * 32 + nb * 8 + (lane & 3) * 2;
                float2 v0 = make_float2(acc[mb][nb][0] + bias[c], acc[mb][nb][1] + bias[c + 1]);
                float2 v1 = make_float2(acc[mb][nb][2] + bias[c], acc[mb][nb][3] + bias[c + 1]);
                *(float2*)&outp[(size_t)r * DM + c]       = v0;
                *(float2*)&outp[(size_t)(r + 8) * DM + c] = v1;
            }
        }
    }
#undef LOAD_STAGE
}

// ---------------------------------------------------------------------------
// fp16 HMMA flash attention, 64-key chunks, split-KEY warp specialization,
// fixed-max softmax (masked -> exp 0), plain-add merge. Band mask applied
// only on edge chunks: a chunk is mask-free iff -192 <= kb - qs <= 192
// (keys never exceed SEQ: ks0/ke/chunks are 64-aligned and clamped).
// Smem: [Q][K0][K1][V0][V1] (5 x 64x72 fp16).
// ---------------------------------------------------------------------------
#define KST 72
#define ATILE (64 * KST)
#define ATB   (ATILE * 2)                        // 9216
#define ATTN_SMEM (5 * ATB)                      // 46080

__global__ __launch_bounds__(256, 2) void attn_kernel()
{
    extern __shared__ __half smb[];
    const uint32_t sm0 = smem_u32(smb);

    const int qt = blockIdx.x;
    const int bh = blockIdx.y;
    const int b  = bh >> 4;
    const int h  = bh & 15;
    const int tid  = threadIdx.x;
    const int w    = tid >> 5;
    const int wq   = w & 3;
    const int wk   = w >> 2;
    const int lane = tid & 31;
    const int qs = qt * 64;

    const size_t hoff = (size_t)b * SEQ * DM + h * HD;
    const __half* __restrict__ Qg = g_Qh + hoff;
    const __half* __restrict__ Kg = g_Kh + hoff;
    const __half* __restrict__ Vg = g_Vh + hoff;

    int ks0 = qs - WIN; if (ks0 < 0) ks0 = 0;
    int ke  = qs + 64 + WIN; if (ke > SEQ) ke = SEQ;
    const int nc = (ke - ks0) >> 6;

#define PREF(ci_)                                                                \
    do {                                                                         \
        int kb_ = ks0 + (ci_) * 64;                                              \
        uint32_t st_ = ((ci_) & 1) * ATB;                                        \
        _Pragma("unroll")                                                        \
        for (int i_ = 0; i_ < 2; i_++) {                                         \
            int idx_ = tid + i_ * 256;                                           \
            int r_ = idx_ >> 3, c_ = idx_ & 7;                                   \
            uint32_t doff_ = (uint32_t)(r_ * KST + c_ * 8) * 2;                  \
            size_t g_ = (size_t)(kb_ + r_) * DM + c_ * 8;                        \
            cpasync16(sm0 + 1 * ATB + st_ + doff_, Kg + g_);                     \
            cpasync16(sm0 + 3 * ATB + st_ + doff_, Vg + g_);                     \
        }                                                                        \
    } while (0)

    PREF(0);
    CP_COMMIT();

    for (int i = tid; i < 64 * 8; i += 256) {
        int r = i >> 3, c = i & 7;
        *(uint4*)&smb[r * KST + c * 8] = *(const uint4*)(Qg + (size_t)(qs + r) * DM + c * 8);
    }
    __syncthreads();

    const int a_r  = (lane & 7) + ((lane >> 3) & 1) * 8;
    const int a_kc = (lane >> 4) * 8;
    uint32_t qa[4][4];
#pragma unroll
    for (int kk = 0; kk < 4; kk++) {
        uint32_t off = (uint32_t)((wq * 16 + a_r) * KST + kk * 16 + a_kc) * 2;
        ldsm4(qa[kk], sm0 + off);
    }

    float O[8][4];
#pragma unroll
    for (int t = 0; t < 8; t++)
#pragma unroll
        for (int e = 0; e < 4; e++) O[t][e] = 0.f;
    float l0 = 0.f, l1 = 0.f;

    const int b_n  = (lane & 7) + (lane >> 4) * 8;
    const int b_kc = ((lane >> 3) & 1) * 8;
    const int v_r  = lane & 15;
    const int v_c  = (lane >> 4) * 8;
    const int q0 = qs + wq * 16 + (lane >> 2);
    const int q1 = q0 + 8;

    for (int ci = 0; ci < nc; ci++) {
        const int kb = ks0 + ci * 64;
        CP_WAIT(0);
        __syncthreads();
        if (ci + 1 < nc) {
            PREF(ci + 1);
            CP_COMMIT();
        }

        const uint32_t Khb = sm0 + 1 * ATB + (ci & 1) * ATB;
        const uint32_t Vhb = sm0 + 3 * ATB + (ci & 1) * ATB;

        float S[4][4];
#pragma unroll
        for (int t = 0; t < 4; t++)
#pragma unroll
            for (int e = 0; e < 4; e++) S[t][e] = 0.f;

#pragma unroll
        for (int kk = 0; kk < 4; kk++) {
#pragma unroll
            for (int nt = 0; nt < 2; nt++) {
                uint32_t kh[4];
                uint32_t off = (uint32_t)((wk * 32 + nt * 16 + b_n) * KST + kk * 16 + b_kc) * 2;
                ldsm4(kh, Khb + off);
                mma16816(S[nt * 2 + 0], qa[kk], &kh[0]);
                mma16816(S[nt * 2 + 1], qa[kk], &kh[2]);
            }
        }

        // ---- band mask only on edge chunks (uniform per-CTA branch)
        if (kb - qs < -192 || kb - qs > 192) {
            const int kc = kb + wk * 32 + 2 * (lane & 3);
#pragma unroll
            for (int j = 0; j < 4; j++) {
                int d0 = kc + j * 8 - q0 + WIN;
                S[j][0] = ((unsigned)d0 <= 2u * WIN)       ? S[j][0] : -1e30f;
                S[j][1] = ((unsigned)(d0 + 1) <= 2u * WIN) ? S[j][1] : -1e30f;
                S[j][2] = ((unsigned)(d0 - 8) <= 2u * WIN) ? S[j][2] : -1e30f;
                S[j][3] = ((unsigned)(d0 - 7) <= 2u * WIN) ? S[j][3] : -1e30f;
            }
        }

        // ---- fixed-max softmax: P = exp(S), lane-local l
#pragma unroll
        for (int j = 0; j < 4; j++) {
            S[j][0] = __expf(S[j][0]);
            S[j][1] = __expf(S[j][1]);
            S[j][2] = __expf(S[j][2]);
            S[j][3] = __expf(S[j][3]);
            l0 += S[j][0] + S[j][1];
            l1 += S[j][2] + S[j][3];
        }

        // ---- PV over warp's 32 keys
#pragma unroll
        for (int kk = 0; kk < 2; kk++) {
            uint32_t pa[4];
            const float* sj0 = S[2 * kk];
            const float* sj1 = S[2 * kk + 1];
            pa[0] = pkh(sj0[0], sj0[1]);
            pa[1] = pkh(sj0[2], sj0[3]);
            pa[2] = pkh(sj1[0], sj1[1]);
            pa[3] = pkh(sj1[2], sj1[3]);
#pragma unroll
            for (int nt = 0; nt < 4; nt++) {
                uint32_t vh[4];
                uint32_t off = (uint32_t)((wk * 32 + kk * 16 + v_r) * KST + nt * 16 + v_c) * 2;
                ldsm4t(vh, Vhb + off);
                mma16816(O[nt * 2 + 0], pa, &vh[0]);
                mma16816(O[nt * 2 + 1], pa, &vh[2]);
            }
        }
    }

    l0 += __shfl_xor_sync(0xffffffffu, l0, 1);
    l0 += __shfl_xor_sync(0xffffffffu, l0, 2);
    l1 += __shfl_xor_sync(0xffffffffu, l1, 1);
    l1 += __shfl_xor_sync(0xffffffffu, l1, 2);

    __syncthreads();
    float* mrg = (float*)smb;
    const int slot = (wq * 32 + lane) * 35;
    if (wk == 1) {
        mrg[slot + 0] = l0; mrg[slot + 1] = l1;
#pragma unroll
        for (int t = 0; t < 8; t++)
#pragma unroll
            for (int e = 0; e < 4; e++) mrg[slot + 2 + t * 4 + e] = O[t][e];
    }
    __syncthreads();
    if (wk == 0) {
        float L0 = l0 + mrg[slot + 0];
        float L1 = l1 + mrg[slot + 1];
        float inv0 = 1.f / L0, inv1 = 1.f / L1;
#pragma unroll
        for (int t = 0; t < 8; t++) {
            float v0 = (O[t][0] + mrg[slot + 2 + t * 4 + 0]) * inv0;
            float v1 = (O[t][1] + mrg[slot + 2 + t * 4 + 1]) * inv0;
            float v2 = (O[t][2] + mrg[slot + 2 + t * 4 + 2]) * inv1;
            float v3 = (O[t][3] + mrg[slot + 2 + t * 4 + 3]) * inv1;
            int c = h * HD + t * 8 + 2 * (lane & 3);
            *(uint32_t*)&g_Ch[((size_t)b * SEQ + q0) * DM + c] = pkh(v0, v1);
            *(uint32_t*)&g_Ch[((size_t)b * SEQ + q1) * DM + c] = pkh(v2, v3);
        }
    }
#undef PREF
}

// ---------------------------------------------------------------------------
extern "C" void kernel_launch(void* const* d_in, const int* in_sizes, int n_in,
                              void* d_out, int out_size)
{
    const float* x  = (const float*)d_in[0];
    const float* Wq = (const float*)d_in[1];
    const float* Wk = (const float*)d_in[2];
    const float* Wv = (const float*)d_in[3];
    const float* Wo = (const float*)d_in[4];
    const float* bo = (const float*)d_in[5];
    float* out = (float*)d_out;

    cudaFuncSetAttribute(mm_kernel, cudaFuncAttributeMaxDynamicSharedMemorySize, MM_SMEM);
    cudaFuncSetAttribute(attn_kernel, cudaFuncAttributeMaxDynamicSharedMemorySize, ATTN_SMEM);

    split_kernel<<<(MROWS * DM) / (4 * 256), 256>>>(x);
    splitT_kernel<<<dim3(DM / 32, DM / 32, 4), dim3(32, 8)>>>(Wq, Wk, Wv, Wo);

    mm_kernel<<<dim3(DM / 128, MROWS / 256, 3), 512, MM_SMEM>>>(nullptr, nullptr, 0);

    attn_kernel<<<dim3(SEQ / 64, BATCH * NH), 256, ATTN_SMEM>>>();

    mm_kernel<<<dim3(DM / 128, MROWS / 256, 1), 512, MM_SMEM>>>(bo, out, 1);
}